// round 15
// baseline (speedup 1.0000x reference)
#include <cuda_runtime.h>
#include <cuda_fp16.h>
#include <mma.h>
#include <cstdint>

using namespace nvcuda;

#define TT 2048
#define EE 1024
#define HSZ 128
#define MROWS 65536
#define NBATCH 32
// SCALE * log2(e): exp(s) == exp2(s_scaled) with this folded in
#define QSCALE 0.1275225094418865f

// Q/K/V scratch in half (Q pre-scaled by SCALE*log2e via g_Wh).
__device__ __half g_Q[(size_t)MROWS * HSZ];
__device__ __half g_K[(size_t)MROWS * HSZ];
__device__ __half g_V[(size_t)MROWS * HSZ];
// pre-converted weights, [w][e][hs] half, Wq pre-scaled
__device__ __half g_Wh[3 * EE * HSZ];

__device__ __forceinline__ uint32_t smem_u32(const void* p) {
    uint32_t a;
    asm("{ .reg .u64 t; cvta.to.shared.u64 t, %1; cvt.u32.u64 %0, t; }"
        : "=r"(a) : "l"(p));
    return a;
}
__device__ __forceinline__ void cp16(uint32_t dst, const void* src) {
    asm volatile("cp.async.cg.shared.global [%0], [%1], 16;"
                 :: "r"(dst), "l"(src) : "memory");
}
#define CP_COMMIT() asm volatile("cp.async.commit_group;" ::: "memory")
#define CP_WAIT(n)  asm volatile("cp.async.wait_group %0;" :: "n"(n) : "memory")
#define PAIR_BAR(id) \
    asm volatile("bar.sync %0, 64;" :: "r"(id) : "memory")

__device__ __forceinline__ float fexp2(float x) {
    float r;
    asm("ex2.approx.f32 %0, %1;" : "=f"(r) : "f"(x));
    return r;
}
__device__ __forceinline__ void mma16816(float* c, const uint32_t* a,
                                         const uint32_t* b) {
    asm volatile("mma.sync.aligned.m16n8k16.row.col.f32.f16.f16.f32 "
        "{%0,%1,%2,%3}, {%4,%5,%6,%7}, {%8,%9}, {%0,%1,%2,%3};"
        : "+f"(c[0]), "+f"(c[1]), "+f"(c[2]), "+f"(c[3])
        : "r"(a[0]), "r"(a[1]), "r"(a[2]), "r"(a[3]),
          "r"(b[0]), "r"(b[1]));
}
__device__ __forceinline__ void ldsm_x4(uint32_t* r, uint32_t a) {
    asm volatile("ldmatrix.sync.aligned.m8n8.x4.shared.b16 {%0,%1,%2,%3}, [%4];"
        : "=r"(r[0]), "=r"(r[1]), "=r"(r[2]), "=r"(r[3]) : "r"(a));
}
__device__ __forceinline__ void ldsm_x4_t(uint32_t* r, uint32_t a) {
    asm volatile("ldmatrix.sync.aligned.m8n8.x4.trans.shared.b16 {%0,%1,%2,%3}, [%4];"
        : "=r"(r[0]), "=r"(r[1]), "=r"(r[2]), "=r"(r[3]) : "r"(a));
}

// ============================================================================
// Pre-kernel: convert Wk/Wq/Wv fp32 -> g_Wh half, folding QSCALE into Wq.
// ============================================================================
__global__ void __launch_bounds__(256) wconv_kernel(
    const float* __restrict__ Wk, const float* __restrict__ Wq,
    const float* __restrict__ Wv)
{
    const int t = blockIdx.x * 256 + threadIdx.x;   // 0..49151
    const int w = t >> 14;
    const int off = (t & 16383) * 8;
    const float* src = (w == 0) ? Wk : ((w == 1) ? Wq : Wv);
    const float sc = (w == 1) ? QSCALE : 1.0f;
    float4 a = *(const float4*)(src + off);
    float4 b = *(const float4*)(src + off + 4);
    union { uint4 q; __half2 h[4]; } o;
    o.h[0] = __floats2half2_rn(a.x * sc, a.y * sc);
    o.h[1] = __floats2half2_rn(a.z * sc, a.w * sc);
    o.h[2] = __floats2half2_rn(b.x * sc, b.y * sc);
    o.h[3] = __floats2half2_rn(b.z * sc, b.w * sc);
    *(uint4*)(g_Wh + (size_t)w * (EE * HSZ) + off) = o.q;
}

// ============================================================================
// Projection v5: 128-thr CTAs, BM=64, grid (1024, 3), 3 CTAs/SM.
// Warp tile 32x64 (same as R11): warp_m = wid&1, warp_n = wid>>1.
// X fp32->half cvt at staging (reg prefetch); W from g_Wh (half, reg prefetch).
// smem: As[2][64][40]h (10240) Bs[2][32][136]h (17408) scr 4x[16][20]f (5120)
// ============================================================================
__global__ void __launch_bounds__(128, 3) proj_kernel(
    const float* __restrict__ xh, const float* __restrict__ xb)
{
    __shared__ __align__(16) __half As[2][64][40];
    __shared__ __align__(16) __half Bs[2][32][136];
    __shared__ __align__(16) float  scr[4][16][20];

    const int m0 = blockIdx.x * 64;
    const int w  = blockIdx.y;
    const float* X = (m0 < MROWS / 2) ? xh + (size_t)m0 * EE
                                      : xb + (size_t)(m0 - MROWS / 2) * EE;
    const __half* Wg = g_Wh + (size_t)w * (EE * HSZ);
    __half* Out = (w == 0) ? g_K : ((w == 1) ? g_Q : g_V);

    const int tid = threadIdx.x, wid = tid >> 5, lane = tid & 31;
    const int warp_m = wid & 1, warp_n = wid >> 1;

    wmma::fragment<wmma::accumulator, 16, 16, 16, float> acc[2][4];
    #pragma unroll
    for (int i = 0; i < 2; i++)
        #pragma unroll
        for (int j = 0; j < 4; j++)
            wmma::fill_fragment(acc[i][j], 0.0f);

    // maps: X 64x32 fp32 = 512 float4 -> 4/thread; W 32x128 half = 512 uint4 -> 4/thread
    const int rX = tid >> 3,  cX = (tid & 7) * 4;     // +16 rows per iter
    const int rW = tid >> 4,  cW16 = (tid & 15);      // +8 rows per iter

    // stage chunk 0
    #pragma unroll
    for (int i = 0; i < 4; i++) {
        float4 v = *(const float4*)&X[(size_t)(rX + i * 16) * EE + cX];
        __half2* d = (__half2*)&As[0][rX + i * 16][cX];
        d[0] = __floats2half2_rn(v.x, v.y);
        d[1] = __floats2half2_rn(v.z, v.w);
        uint4 u = *(const uint4*)((const char*)(Wg + (size_t)(rW + i * 8) * HSZ) +
                                  cW16 * 16);
        *(uint4*)((char*)&Bs[0][rW + i * 8][0] + cW16 * 16) = u;
    }
    __syncthreads();

    for (int c = 0; c < 32; c++) {
        const int b = c & 1;
        float4 px[4];
        uint4  pw[4];
        if (c + 1 < 32) {
            #pragma unroll
            for (int i = 0; i < 4; i++) {
                px[i] = *(const float4*)&X[(size_t)(rX + i * 16) * EE +
                                           (c + 1) * 32 + cX];
                pw[i] = *(const uint4*)((const char*)(Wg +
                            (size_t)((c + 1) * 32 + rW + i * 8) * HSZ) + cW16 * 16);
            }
        }
        #pragma unroll
        for (int kk = 0; kk < 32; kk += 16) {
            wmma::fragment<wmma::matrix_a, 16, 16, 16, __half,
                           wmma::row_major> a[2];
            wmma::fragment<wmma::matrix_b, 16, 16, 16, __half,
                           wmma::row_major> bf[4];
            #pragma unroll
            for (int i = 0; i < 2; i++)
                wmma::load_matrix_sync(a[i], &As[b][warp_m * 32 + i * 16][kk], 40);
            #pragma unroll
            for (int j = 0; j < 4; j++)
                wmma::load_matrix_sync(bf[j], &Bs[b][kk][warp_n * 64 + j * 16], 136);
            #pragma unroll
            for (int i = 0; i < 2; i++)
                #pragma unroll
                for (int j = 0; j < 4; j++)
                    wmma::mma_sync(acc[i][j], a[i], bf[j], acc[i][j]);
        }
        if (c + 1 < 32) {
            const int nb = (c + 1) & 1;
            #pragma unroll
            for (int i = 0; i < 4; i++) {
                __half2* d = (__half2*)&As[nb][rX + i * 16][cX];
                d[0] = __floats2half2_rn(px[i].x, px[i].y);
                d[1] = __floats2half2_rn(px[i].z, px[i].w);
                *(uint4*)((char*)&Bs[nb][rW + i * 8][0] + cW16 * 16) = pw[i];
            }
        }
        __syncthreads();
    }

    // epilogue: acc -> half gmem via per-warp scratch (scale pre-folded in W)
    const int row = lane >> 1, c0 = (lane & 1) * 8;
    #pragma unroll
    for (int i = 0; i < 2; i++)
        #pragma unroll
        for (int j = 0; j < 4; j++) {
            __syncwarp();
            wmma::store_matrix_sync(&scr[wid][0][0], acc[i][j], 20,
                                    wmma::mem_row_major);
            __syncwarp();
            float4 u = *(float4*)&scr[wid][row][c0];
            float4 v = *(float4*)&scr[wid][row][c0 + 4];
            union { uint4 q; __half2 h[4]; } o;
            o.h[0] = __floats2half2_rn(u.x, u.y);
            o.h[1] = __floats2half2_rn(u.z, u.w);
            o.h[2] = __floats2half2_rn(v.x, v.y);
            o.h[3] = __floats2half2_rn(v.z, v.w);
            const int gm = m0 + warp_m * 32 + i * 16 + row;
            const int gc = warp_n * 64 + j * 16 + c0;
            *(uint4*)&Out[(size_t)gm * HSZ + gc] = o.q;
        }
}

// ============================================================================
// Fused flash attention v5 (unchanged from R14): 128-thr CTAs, 2/SM.
// ============================================================================
#define SM_K(b) ((b) * 17408)
#define SM_V(b) (34816 + (b) * 17408)
#define SM_PH   69632
#define SM_LP   78848
#define A_SMEM  79360

__global__ void __launch_bounds__(128, 2) attn_kernel(float* __restrict__ out)
{
    extern __shared__ __align__(16) char sm[];
    const uint32_t sa = smem_u32(sm);
    const uint32_t ph = sa + SM_PH;
    float* smLp = (float*)(sm + SM_LP);
    const int tid = threadIdx.x, wid = tid >> 5, lane = tid & 31;
    const int warp_m = wid & 1, warp_n = wid >> 1;
    const int tg = lane >> 2, tq = lane & 3;
    const int sb = blockIdx.y, q0 = blockIdx.x * 64;
    const __half* Qg = g_Q + ((size_t)sb * TT + q0) * HSZ;
    const __half* Kg = g_K + (size_t)sb * TT * HSZ;
    const __half* Vg = g_V + (size_t)sb * TT * HSZ;

    #pragma unroll
    for (int t = 0; t < 8; t++) {
        int idx = tid + t * 128, r = idx >> 4, c16 = idx & 15;
        cp16(sa + SM_K(0) + r * 272 + c16 * 16,
             (const char*)Kg + (size_t)r * 256 + c16 * 16);
        cp16(sa + SM_V(0) + r * 272 + c16 * 16,
             (const char*)Vg + (size_t)r * 256 + c16 * 16);
    }
    CP_COMMIT();

    uint32_t aq[2][8][4];
    #pragma unroll
    for (int i = 0; i < 2; i++)
        #pragma unroll
        for (int k = 0; k < 8; k++) {
            const __half* p = Qg + (size_t)(warp_m * 32 + i * 16 + tg) * HSZ +
                              k * 16 + tq * 2;
            aq[i][k][0] = *(const uint32_t*)p;
            aq[i][k][1] = *(const uint32_t*)(p + 8 * HSZ);
            aq[i][k][2] = *(const uint32_t*)(p + 8);
            aq[i][k][3] = *(const uint32_t*)(p + 8 * HSZ + 8);
        }

    float acc_o[2][8][4];
    #pragma unroll
    for (int i = 0; i < 2; i++)
        #pragma unroll
        for (int j = 0; j < 8; j++)
            #pragma unroll
            for (int e = 0; e < 4; e++)
                acc_o[i][j][e] = 0.0f;
    float Lc[4] = { 0.0f, 0.0f, 0.0f, 0.0f };

    const int l8 = lane & 7, sel = lane >> 3;
    const uint32_t koff = (uint32_t)((l8 + ((sel >> 1) & 1) * 8) * 272 +
                                     (sel & 1) * 16);
    const uint32_t voff = (uint32_t)((l8 + (sel & 1) * 8) * 272 +
                                     ((sel >> 1) & 1) * 16);
    const uint32_t poff = (uint32_t)((l8 + (sel & 1) * 8) * 144 +
                                     ((sel >> 1) & 1) * 16);

    for (int c = 0; c < 32; c++) {
        CP_WAIT(0);
        __syncthreads();
        if (c + 1 < 32) {
            const char* Kc = (const char*)Kg + (size_t)(c + 1) * 64 * 256;
            const char* Vc = (const char*)Vg + (size_t)(c + 1) * 64 * 256;
            #pragma unroll
            for (int t = 0; t < 8; t++) {
                int idx = tid + t * 128, r = idx >> 4, c16 = idx & 15;
                cp16(sa + SM_K((c + 1) & 1) + r * 272 + c16 * 16,
                     Kc + (size_t)r * 256 + c16 * 16);
                cp16(sa + SM_V((c + 1) & 1) + r * 272 + c16 * 16,
                     Vc + (size_t)r * 256 + c16 * 16);
            }
            CP_COMMIT();
        }
        const uint32_t kb = sa + SM_K(c & 1);
        const uint32_t vb = sa + SM_V(c & 1);

        float acc_s[2][4][4];
        #pragma unroll
        for (int i = 0; i < 2; i++)
            #pragma unroll
            for (int j = 0; j < 4; j++)
                #pragma unroll
                for (int e = 0; e < 4; e++)
                    acc_s[i][j][e] = 0.0f;
        #pragma unroll
        for (int k = 0; k < 8; k++) {
            uint32_t bk[8];
            ldsm_x4(bk,     kb + (warp_n * 32) * 272 + k * 32 + koff);
            ldsm_x4(bk + 4, kb + (warp_n * 32 + 16) * 272 + k * 32 + koff);
            #pragma unroll
            for (int i = 0; i < 2; i++)
                #pragma unroll
                for (int j = 0; j < 4; j++)
                    mma16816(acc_s[i][j], aq[i][k], &bk[j * 2]);
        }

        uint32_t ap[2][2][4];
        #pragma unroll
        for (int i = 0; i < 2; i++)
            #pragma unroll
            for (int j = 0; j < 4; j++) {
                __half2 h0 = __floats2half2_rn(fexp2(acc_s[i][j][0]),
                                               fexp2(acc_s[i][j][1]));
                __half2 h1 = __floats2half2_rn(fexp2(acc_s[i][j][2]),
                                               fexp2(acc_s[i][j][3]));
                float2 f0 = __half22float2(h0);
                float2 f1 = __half22float2(h1);
                Lc[i * 2 + 0] += f0.x + f0.y;
                Lc[i * 2 + 1] += f1.x + f1.y;
                ap[i][j >> 1][(j & 1) * 2 + 0] = *(uint32_t*)&h0;
                ap[i][j >> 1][(j & 1) * 2 + 1] = *(uint32_t*)&h1;
            }

        PAIR_BAR(1 + warp_m);

        #pragma unroll
        for (int i = 0; i < 2; i++)
            #pragma unroll
            for (int j = 0; j < 4; j++) {
                uint32_t addr = ph + (uint32_t)(warp_m * 32 + i * 16 + tg) * 144 +
                                (uint32_t)(warp_n * 32 + j * 8 + tq * 2) * 2;
                asm volatile("st.shared.b32 [%0], %1;"
                             :: "r"(addr), "r"(ap[i][j >> 1][(j & 1) * 2]));
                asm volatile("st.shared.b32 [%0], %1;"
                             :: "r"(addr + 8 * 144),
                                "r"(ap[i][j >> 1][(j & 1) * 2 + 1]));
            }

        PAIR_BAR(1 + warp_m);

        #pragma unroll
        for (int s = 0; s < 4; s++) {
            uint32_t av[2][4];
            if ((s >> 1) == warp_n) {
                #pragma unroll
                for (int i = 0; i < 2; i++)
                    #pragma unroll
                    for (int e = 0; e < 4; e++)
                        av[i][e] = ap[i][s & 1][e];
            } else {
                #pragma unroll
                for (int i = 0; i < 2; i++)
                    ldsm_x4(av[i], ph + (uint32_t)(warp_m * 32 + i * 16) * 144 +
                                   s * 32 + poff);
            }
            #pragma unroll
            for (int jj = 0; jj < 4; jj++) {
                uint32_t bv[4];
                ldsm_x4_t(bv, vb + (s * 16) * 272 +
                              (warp_n * 64 + jj * 16) * 2 + voff);
                #pragma unroll
                for (int i = 0; i < 2; i++) {
                    mma16816(acc_o[i][jj * 2],     av[i], bv);
                    mma16816(acc_o[i][jj * 2 + 1], av[i], bv + 2);
                }
            }
        }
    }

    #pragma unroll
    for (int q = 0; q < 4; q++) {
        Lc[q] += __shfl_xor_sync(0xffffffffu, Lc[q], 1);
        Lc[q] += __shfl_xor_sync(0xffffffffu, Lc[q], 2);
    }
    if (tq == 0) {
        #pragma unroll
        for (int i = 0; i < 2; i++)
            #pragma unroll
            for (int h = 0; h < 2; h++)
                smLp[(warp_m * 32 + i * 16 + h * 8 + tg) * 2 + warp_n] =
                    Lc[i * 2 + h];
    }
    __syncthreads();

    #pragma unroll
    for (int i = 0; i < 2; i++) {
        const int r0 = warp_m * 32 + i * 16 + tg;
        const float inv0 = 1.0f / (smLp[r0 * 2] + smLp[r0 * 2 + 1]);
        const float inv1 = 1.0f / (smLp[(r0 + 8) * 2] + smLp[(r0 + 8) * 2 + 1]);
        float* O0 = out + ((size_t)sb * TT + q0 + r0) * HSZ + warp_n * 64 + tq * 2;
        float* O1 = O0 + 8 * HSZ;
        #pragma unroll
        for (int j = 0; j < 8; j++) {
            float2 v0 = { acc_o[i][j][0] * inv0, acc_o[i][j][1] * inv0 };
            float2 v1 = { acc_o[i][j][2] * inv1, acc_o[i][j][3] * inv1 };
            *(float2*)(O0 + j * 8) = v0;
            *(float2*)(O1 + j * 8) = v1;
        }
    }
}

// ============================================================================
extern "C" void kernel_launch(void* const* d_in, const int* in_sizes, int n_in,
                              void* d_out, int out_size)
{
    const float* x_head = (const float*)d_in[0];
    const float* x_body = (const float*)d_in[1];
    const float* Wk     = (const float*)d_in[2];
    const float* Wq     = (const float*)d_in[3];
    const float* Wv     = (const float*)d_in[4];
    float* out = (float*)d_out;

    cudaFuncSetAttribute(attn_kernel,
                         cudaFuncAttributeMaxDynamicSharedMemorySize, A_SMEM);

    wconv_kernel<<<192, 256>>>(Wk, Wq, Wv);
    proj_kernel<<<dim3(MROWS / 64, 3, 1), 128>>>(x_head, x_body);
    attn_kernel<<<dim3(TT / 64, NBATCH, 1), 128, A_SMEM>>>(out);
}